// round 11
// baseline (speedup 1.0000x reference)
#include <cuda_runtime.h>
#include <math.h>

#define B_    16
#define T_    4
#define CIN_  128
#define COUT_ 128
#define H_    56
#define W_    56
#define HW_   (H_*W_)

#define CT    128    // couts per block (all of them)
#define CPT   8      // couts per thread
#define PX    4      // pixels per thread
#define NTHREADS 224 // cg = tid&15 (16 cout-groups x 8 couts), wg = tid>>4 (14 width-groups)

// dynamic smem: one scalar input row: s_in[128 ci][60]
// index k holds input col (k-1): cols -1..56 at idx 0..57; 58,59 pad.
// ow0 = wg*4 -> idx ow0 is 16B-aligned (kw0 window = idx ow0..ow0+3).
#define SROW   60
#define SMEM_BYTES (CIN_*SROW*4)        // 30720 -> 2 CTAs/SM

typedef unsigned long long u64;

// transposed weights: wT[kh][kw][ci][co]
__device__ float g_wT[9*CIN_*COUT_];

// ---------------------------------------------------------------------------
__global__ void wt_kernel(const float* __restrict__ w) {
    int i = blockIdx.x*256 + threadIdx.x;          // over co*ci*9
    if (i >= COUT_*CIN_*9) return;
    int co  = i / (CIN_*9);
    int rem = i - co*(CIN_*9);
    int ci  = rem / 9;
    int k   = rem - ci*9;
    g_wT[(k*CIN_ + ci)*COUT_ + co] = w[i];
}

// ---------------------------------------------------------------------------
// Packed fp32x2 helpers. Each lane of fma.rn.f32x2 rounds identically to
// scalar FFMA, so a packed chain == two independent scalar chains bitwise.
// ---------------------------------------------------------------------------
__device__ __forceinline__ void ffma2(u64 &d, u64 a, u64 b) {
    asm("fma.rn.f32x2 %0, %1, %2, %0;" : "+l"(d) : "l"(a), "l"(b));
}
__device__ __forceinline__ u64 pack2(float v) {   // {v, v} — 1 MOV in SASS
    u64 r; asm("mov.b64 %0, {%1, %1};" : "=l"(r) : "f"(v)); return r;
}
__device__ __forceinline__ void unpack2(u64 v, float &lo, float &hi) {
    asm("mov.b64 {%0, %1}, %2;" : "=f"(lo), "=f"(hi) : "l"(v));
}

// one ci step: 8 couts (4 f32x2 weight pairs) x 4 dup'd input pixels -> 16 FFMA2
#define CI_STEP8(WA, WB, I0, I1, I2, I3)                                   \
    do {                                                                   \
        ffma2(acc2[0][0], (WA).x, (I0)); ffma2(acc2[1][0], (WA).y, (I0));  \
        ffma2(acc2[2][0], (WB).x, (I0)); ffma2(acc2[3][0], (WB).y, (I0));  \
        ffma2(acc2[0][1], (WA).x, (I1)); ffma2(acc2[1][1], (WA).y, (I1));  \
        ffma2(acc2[2][1], (WB).x, (I1)); ffma2(acc2[3][1], (WB).y, (I1));  \
        ffma2(acc2[0][2], (WA).x, (I2)); ffma2(acc2[1][2], (WA).y, (I2));  \
        ffma2(acc2[2][2], (WB).x, (I2)); ffma2(acc2[3][2], (WB).y, (I2));  \
        ffma2(acc2[0][3], (WA).x, (I3)); ffma2(acc2[1][3], (WA).y, (I3));  \
        ffma2(acc2[2][3], (WB).x, (I3)); ffma2(acc2[3][3], (WB).y, (I3));  \
    } while (0)

// ---------------------------------------------------------------------------
// Conv, reference-order chain k = (kh major, kw, ci minor); one fp32
// accumulator per output (packed in cout-pairs). kh outer -> stage exactly one
// scalar input row per (t,kh). Thread: 8 couts x 4 pixels, 1 output row.
// ---------------------------------------------------------------------------
__global__ __launch_bounds__(NTHREADS, 2)
void conv_spike_kernel(const float* __restrict__ x,
                       const float* __restrict__ cbias,
                       const float* __restrict__ gamma,
                       const float* __restrict__ beta,
                       const float* __restrict__ rmean,
                       const float* __restrict__ rvar,
                       const float* __restrict__ alpha,
                       float* __restrict__ out)
{
    extern __shared__ __align__(16) float s_in[];  // [128][60] scalar

    const int oh  = blockIdx.x;        // 0..55 (output row)
    const int b   = blockIdx.z;        // 0..15
    const int tid = threadIdx.x;       // 0..223
    const int cg  = tid & 15;          // cout group 0..15 (fast across lanes)
    const int wg  = tid >> 4;          // width group 0..13
    const int ow0 = wg*PX;
    const int co0 = cg*CPT;

    float m[CPT][PX];                  // membrane accumulator (fp32, ascending t)

    #pragma unroll 1
    for (int t = 0; t < T_; t++) {
        const float* xbt = x + (b*T_ + t)*CIN_*HW_;

        // single fp32 accumulator per (cout,pixel), packed in cout-pairs
        u64 acc2[CPT/2][PX];
        #pragma unroll
        for (int q = 0; q < CPT/2; q++)
            #pragma unroll
            for (int p = 0; p < PX; p++) acc2[q][p] = 0ull;

        #pragma unroll 1
        for (int kh = 0; kh < 3; kh++) {
            const int ih = oh - 1 + kh;

            __syncthreads();           // previous sweep done before overwrite
            if ((unsigned)ih < (unsigned)H_) {
                // interior: 128 ci x 14 float4 gmem reads, scalar smem stores
                #pragma unroll 1
                for (int idx = tid; idx < CIN_*14; idx += NTHREADS) {
                    int ci = idx / 14;
                    int g  = idx - ci*14;
                    float4 v = *(const float4*)(xbt + ci*HW_ + ih*W_ + g*4);
                    float* d = s_in + ci*SROW + 1 + g*4;
                    d[0] = v.x; d[1] = v.y; d[2] = v.z; d[3] = v.w;
                }
                // halo columns (-1 at idx 0, 56 at idx 57) are zero
                #pragma unroll 1
                for (int ci = tid; ci < CIN_; ci += NTHREADS) {
                    s_in[ci*SROW]      = 0.f;
                    s_in[ci*SROW + 57] = 0.f;
                }
            } else {
                #pragma unroll 1
                for (int idx = tid; idx < CIN_*SROW; idx += NTHREADS)
                    s_in[idx] = 0.f;
            }
            __syncthreads();

            // chain: kw 0..2 in order, ci 0..127 inner (reference k-order).
            {   // kw = 0: idx ow0..ow0+3, 16B-aligned -> 1 LDS.128
                const float* wt = g_wT + ((kh*3 + 0)*CIN_)*COUT_ + co0;
                const float* ib = s_in + ow0;
                #pragma unroll 4
                for (int ci = 0; ci < CIN_; ci++) {
                    ulonglong2 wpA = *(const ulonglong2*)(wt + ci*COUT_);
                    ulonglong2 wpB = *(const ulonglong2*)(wt + ci*COUT_ + 4);
                    float4 v = *(const float4*)(ib + ci*SROW);
                    CI_STEP8(wpA, wpB, pack2(v.x), pack2(v.y), pack2(v.z), pack2(v.w));
                }
            }
            {   // kw = 1: idx ow0+1..ow0+4 -> LDS.128 (use .y.z.w) + LDS.32
                const float* wt = g_wT + ((kh*3 + 1)*CIN_)*COUT_ + co0;
                const float* ib = s_in + ow0;
                #pragma unroll 4
                for (int ci = 0; ci < CIN_; ci++) {
                    ulonglong2 wpA = *(const ulonglong2*)(wt + ci*COUT_);
                    ulonglong2 wpB = *(const ulonglong2*)(wt + ci*COUT_ + 4);
                    float4 v = *(const float4*)(ib + ci*SROW);
                    float  s4 = ib[ci*SROW + 4];
                    CI_STEP8(wpA, wpB, pack2(v.y), pack2(v.z), pack2(v.w), pack2(s4));
                }
            }
            {   // kw = 2: idx ow0+2..ow0+5 -> 2x LDS.64 (8B-aligned)
                const float* wt = g_wT + ((kh*3 + 2)*CIN_)*COUT_ + co0;
                const float* ib = s_in + ow0 + 2;
                #pragma unroll 4
                for (int ci = 0; ci < CIN_; ci++) {
                    ulonglong2 wpA = *(const ulonglong2*)(wt + ci*COUT_);
                    ulonglong2 wpB = *(const ulonglong2*)(wt + ci*COUT_ + 4);
                    float2 v01 = *(const float2*)(ib + ci*SROW);
                    float2 v23 = *(const float2*)(ib + ci*SROW + 2);
                    CI_STEP8(wpA, wpB, pack2(v01.x), pack2(v01.y), pack2(v23.x), pack2(v23.y));
                }
            }
        }

        // --- per-timestep epilogue: replicate reference fp32 roundings ---
        // (BN constants recomputed here each t to keep hot-loop registers low)
        const float tscale = (float)(1 << (3 - t));   // exact power of 2
        #pragma unroll
        for (int c = 0; c < CPT; c++) {
            int co = co0 + c;
            float cb = cbias[co];
            float mn = rmean[co];
            float iv = __fmul_rn(__fdiv_rn(1.0f, __fsqrt_rn(__fadd_rn(rvar[co], 1e-5f))),
                                 gamma[co]);
            float bt = beta[co];
            int q = c >> 1, half = c & 1;
            #pragma unroll
            for (int p = 0; p < PX; p++) {
                float al, ah;
                unpack2(acc2[q][p], al, ah);
                float y = half ? ah : al;                  // raw conv accumulator
                y = __fadd_rn(y, cb);                      // + bias
                y = __fmul_rn(y, 1.875f);                  // * (2^T-1)/2^(T-1)
                y = __fmul_rn(__fsub_rn(y, mn), iv);       // BN sub, mul
                y = __fadd_rn(y, bt);                      // + beta
                y = __fdiv_rn(y, 15.0f);                   // / (2^T-1)
                float prod = __fmul_rn(y, tscale);         // exact (power of 2)
                m[c][p] = (t == 0) ? prod : __fadd_rn(m[c][p], prod);
            }
        }
    }

    // ----- spike scan (identical fp32 ops to reference) -----
    const float thr = __fdiv_rn(__fmul_rn(*alpha, 8.0f), 15.0f);
    const float coef[4] = {0.9375f, 0.875f, 0.75f, 0.5f};

    #pragma unroll 1
    for (int c = 0; c < CPT; c++) {
        int co = co0 + c;
        float mem[PX];
        #pragma unroll
        for (int p = 0; p < PX; p++) mem[p] = m[c][p];
        float* obase = out + (b*T_*COUT_ + co)*HW_ + oh*W_ + ow0;
        #pragma unroll
        for (int dt = 0; dt < 4; dt++) {
            float cthr = __fmul_rn(coef[dt], thr);
            float4 o;
            float s0 = (mem[0] >= cthr) ? thr : 0.f; mem[0] = __fmul_rn(__fsub_rn(mem[0], s0), 2.f);
            float s1 = (mem[1] >= cthr) ? thr : 0.f; mem[1] = __fmul_rn(__fsub_rn(mem[1], s1), 2.f);
            float s2 = (mem[2] >= cthr) ? thr : 0.f; mem[2] = __fmul_rn(__fsub_rn(mem[2], s2), 2.f);
            float s3 = (mem[3] >= cthr) ? thr : 0.f; mem[3] = __fmul_rn(__fsub_rn(mem[3], s3), 2.f);
            o.x = s0; o.y = s1; o.z = s2; o.w = s3;
            *(float4*)(obase + dt*COUT_*HW_) = o;
        }
    }
}

// ---------------------------------------------------------------------------
extern "C" void kernel_launch(void* const* d_in, const int* in_sizes, int n_in,
                              void* d_out, int out_size) {
    const float* x     = (const float*)d_in[0];
    const float* convw = (const float*)d_in[1];
    const float* convb = (const float*)d_in[2];
    const float* gamma = (const float*)d_in[3];
    const float* beta  = (const float*)d_in[4];
    const float* rmean = (const float*)d_in[5];
    const float* rvar  = (const float*)d_in[6];
    const float* alpha = (const float*)d_in[7];
    float* out = (float*)d_out;

    wt_kernel<<<(COUT_*CIN_*9 + 255)/256, 256>>>(convw);

    dim3 grid(H_, 1, B_);   // 56 x 1 x 16 = 896 CTAs
    conv_spike_kernel<<<grid, NTHREADS, SMEM_BYTES>>>(x, convb, gamma, beta,
                                                      rmean, rvar, alpha, out);
}

// round 12
// speedup vs baseline: 1.3736x; 1.3736x over previous
#include <cuda_runtime.h>
#include <math.h>

#define B_    16
#define T_    4
#define CIN_  128
#define COUT_ 128
#define H_    56
#define W_    56
#define HW_   (H_*W_)

#define CT    64     // couts per block
#define CPT   4      // couts per thread
#define PX    4      // pixels per thread
#define RPT   2      // output rows per thread (share weight loads)
#define NTHREADS 224 // cg = tid&15 (16 cout-groups), wg = tid>>4 (14 width-groups)

// dynamic smem layout:
//   s_in[2][128][60]  : two staged input rows (slot s = row oh0-1+kh+s)
//                       idx k holds input col (k-1): cols -1..56 at 0..57
//   sm_m [224][33]    : per-thread membrane (32 used, stride 33 = no conflicts)
#define SROW   60
#define SIN_FLOATS (2*CIN_*SROW)                 // 15360
#define SM_M_OFF   SIN_FLOATS
#define SMEM_BYTES ((SIN_FLOATS + NTHREADS*33)*4) // 91008 -> 2 CTAs/SM (228KB)

typedef unsigned long long u64;

// transposed weights: wT[kh][kw][ci][co]
__device__ float g_wT[9*CIN_*COUT_];

// ---------------------------------------------------------------------------
__global__ void wt_kernel(const float* __restrict__ w) {
    int i = blockIdx.x*256 + threadIdx.x;          // over co*ci*9
    if (i >= COUT_*CIN_*9) return;
    int co  = i / (CIN_*9);
    int rem = i - co*(CIN_*9);
    int ci  = rem / 9;
    int k   = rem - ci*9;
    g_wT[(k*CIN_ + ci)*COUT_ + co] = w[i];
}

// ---------------------------------------------------------------------------
// Packed fp32x2 helpers. Each lane of fma.rn.f32x2 rounds identically to
// scalar FFMA, so a packed chain == two independent scalar chains bitwise.
// ---------------------------------------------------------------------------
__device__ __forceinline__ void ffma2(u64 &d, u64 a, u64 b) {
    asm("fma.rn.f32x2 %0, %1, %2, %0;" : "+l"(d) : "l"(a), "l"(b));
}
__device__ __forceinline__ u64 pack2(float v) {   // {v, v} — 1 MOV in SASS
    u64 r; asm("mov.b64 %0, {%1, %1};" : "=l"(r) : "f"(v)); return r;
}
__device__ __forceinline__ void unpack2(u64 v, float &lo, float &hi) {
    asm("mov.b64 {%0, %1}, %2;" : "=f"(lo), "=f"(hi) : "l"(v));
}

// one (row) step: weight pair WP x 4 dup'd inputs -> 8 FFMA2 into row r's accs
#define ROW_STEP(R, WP, I0, I1, I2, I3)                                         \
    do {                                                                        \
        ffma2(acc2[R][0][0], (WP).x, (I0)); ffma2(acc2[R][1][0], (WP).y, (I0)); \
        ffma2(acc2[R][0][1], (WP).x, (I1)); ffma2(acc2[R][1][1], (WP).y, (I1)); \
        ffma2(acc2[R][0][2], (WP).x, (I2)); ffma2(acc2[R][1][2], (WP).y, (I2)); \
        ffma2(acc2[R][0][3], (WP).x, (I3)); ffma2(acc2[R][1][3], (WP).y, (I3)); \
    } while (0)

// ---------------------------------------------------------------------------
// Conv, reference-order chain k = (kh major, kw, ci minor); one fp32
// accumulator per output (packed in cout-pairs). kh outer -> stage the two
// input rows both thread-rows need. Thread: 4 couts x 4 px x 2 rows.
// ---------------------------------------------------------------------------
__global__ __launch_bounds__(NTHREADS, 2)
void conv_spike_kernel(const float* __restrict__ x,
                       const float* __restrict__ cbias,
                       const float* __restrict__ gamma,
                       const float* __restrict__ beta,
                       const float* __restrict__ rmean,
                       const float* __restrict__ rvar,
                       const float* __restrict__ alpha,
                       float* __restrict__ out)
{
    extern __shared__ __align__(16) float s_in[];  // see layout above
    float* sm_m = s_in + SM_M_OFF;

    const int oh0 = blockIdx.x * RPT;  // rows oh0, oh0+1
    const int ct  = blockIdx.y;        // 0..1
    const int b   = blockIdx.z;        // 0..15
    const int tid = threadIdx.x;       // 0..223
    const int cg  = tid & 15;          // cout group (fast across lanes)
    const int wg  = tid >> 4;          // width group 0..13
    const int ow0 = wg*PX;
    const int co0 = ct*CT + cg*CPT;
    float* mymem = sm_m + tid;         // stride-33 layout: idx i at [i*  ... ]

    #pragma unroll 1
    for (int t = 0; t < T_; t++) {
        const float* xbt = x + (b*T_ + t)*CIN_*HW_;

        // fp32 accumulators: [row][cout-pair][pixel]
        u64 acc2[RPT][CPT/2][PX];
        #pragma unroll
        for (int r = 0; r < RPT; r++)
            #pragma unroll
            for (int q = 0; q < CPT/2; q++)
                #pragma unroll
                for (int p = 0; p < PX; p++) acc2[r][q][p] = 0ull;

        #pragma unroll 1
        for (int kh = 0; kh < 3; kh++) {
            __syncthreads();           // previous sweep done before overwrite
            // stage rows: slot s holds input row oh0-1+kh+s  (s = 0,1)
            #pragma unroll 1
            for (int idx = tid; idx < 2*CIN_*14; idx += NTHREADS) {
                int s   = idx / (CIN_*14);
                int rem = idx - s*(CIN_*14);
                int ci  = rem / 14;
                int g   = rem - ci*14;
                int ih  = oh0 - 1 + kh + s;
                float* d = s_in + (s*CIN_ + ci)*SROW + 1 + g*4;
                if ((unsigned)ih < (unsigned)H_) {
                    float4 v = *(const float4*)(xbt + ci*HW_ + ih*W_ + g*4);
                    d[0] = v.x; d[1] = v.y; d[2] = v.z; d[3] = v.w;
                } else {
                    d[0] = 0.f; d[1] = 0.f; d[2] = 0.f; d[3] = 0.f;
                }
            }
            // halo columns (idx 0 and 57) zero for both slots
            #pragma unroll 1
            for (int sc = tid; sc < 2*CIN_; sc += NTHREADS) {
                s_in[sc*SROW]      = 0.f;
                s_in[sc*SROW + 57] = 0.f;
            }
            __syncthreads();

            // chain: kw 0..2 in order, ci 0..127 inner (reference k-order);
            // one 16B weight load serves both rows (16 FFMA2).
            {   // kw = 0: idx ow0..ow0+3 (16B-aligned)
                const float* wt = g_wT + ((kh*3 + 0)*CIN_)*COUT_ + co0;
                const float* i0 = s_in + ow0;              // slot 0
                const float* i1 = s_in + CIN_*SROW + ow0;  // slot 1
                #pragma unroll 4
                for (int ci = 0; ci < CIN_; ci++) {
                    ulonglong2 wp = *(const ulonglong2*)(wt + ci*COUT_);
                    float4 a = *(const float4*)(i0 + ci*SROW);
                    float4 bv = *(const float4*)(i1 + ci*SROW);
                    ROW_STEP(0, wp, pack2(a.x), pack2(a.y), pack2(a.z), pack2(a.w));
                    ROW_STEP(1, wp, pack2(bv.x), pack2(bv.y), pack2(bv.z), pack2(bv.w));
                }
            }
            {   // kw = 1: idx ow0+1..ow0+4 -> LDS.128 (.y.z.w) + LDS.32
                const float* wt = g_wT + ((kh*3 + 1)*CIN_)*COUT_ + co0;
                const float* i0 = s_in + ow0;
                const float* i1 = s_in + CIN_*SROW + ow0;
                #pragma unroll 4
                for (int ci = 0; ci < CIN_; ci++) {
                    ulonglong2 wp = *(const ulonglong2*)(wt + ci*COUT_);
                    float4 a = *(const float4*)(i0 + ci*SROW);
                    float  a4 = i0[ci*SROW + 4];
                    float4 bv = *(const float4*)(i1 + ci*SROW);
                    float  b4 = i1[ci*SROW + 4];
                    ROW_STEP(0, wp, pack2(a.y), pack2(a.z), pack2(a.w), pack2(a4));
                    ROW_STEP(1, wp, pack2(bv.y), pack2(bv.z), pack2(bv.w), pack2(b4));
                }
            }
            {   // kw = 2: idx ow0+2..ow0+5 -> 2x LDS.64 per row
                const float* wt = g_wT + ((kh*3 + 2)*CIN_)*COUT_ + co0;
                const float* i0 = s_in + ow0 + 2;
                const float* i1 = s_in + CIN_*SROW + ow0 + 2;
                #pragma unroll 4
                for (int ci = 0; ci < CIN_; ci++) {
                    ulonglong2 wp = *(const ulonglong2*)(wt + ci*COUT_);
                    float2 a01 = *(const float2*)(i0 + ci*SROW);
                    float2 a23 = *(const float2*)(i0 + ci*SROW + 2);
                    float2 b01 = *(const float2*)(i1 + ci*SROW);
                    float2 b23 = *(const float2*)(i1 + ci*SROW + 2);
                    ROW_STEP(0, wp, pack2(a01.x), pack2(a01.y), pack2(a23.x), pack2(a23.y));
                    ROW_STEP(1, wp, pack2(b01.x), pack2(b01.y), pack2(b23.x), pack2(b23.y));
                }
            }
        }

        // --- per-timestep epilogue: replicate reference fp32 roundings ---
        const float tscale = (float)(1 << (3 - t));   // exact power of 2
        #pragma unroll 1
        for (int c = 0; c < CPT; c++) {
            int co = co0 + c;
            float cb = cbias[co];
            float mn = rmean[co];
            float iv = __fmul_rn(__fdiv_rn(1.0f, __fsqrt_rn(__fadd_rn(rvar[co], 1e-5f))),
                                 gamma[co]);
            float bt = beta[co];
            int q = c >> 1, half = c & 1;
            #pragma unroll
            for (int r = 0; r < RPT; r++) {
                #pragma unroll
                for (int p = 0; p < PX; p++) {
                    float al, ah;
                    unpack2(acc2[r][q][p], al, ah);
                    float y = half ? ah : al;                  // raw conv accumulator
                    y = __fadd_rn(y, cb);                      // + bias
                    y = __fmul_rn(y, 1.875f);                  // * (2^T-1)/2^(T-1)
                    y = __fmul_rn(__fsub_rn(y, mn), iv);       // BN sub, mul
                    y = __fadd_rn(y, bt);                      // + beta
                    y = __fdiv_rn(y, 15.0f);                   // / (2^T-1)
                    float prod = __fmul_rn(y, tscale);         // exact (power of 2)
                    int mi = ((r*CPT + c)*PX + p)*NTHREADS;    // conflict-free slot
                    mymem[mi] = (t == 0) ? prod : __fadd_rn(mymem[mi], prod);
                }
            }
        }
    }

    // ----- spike scan (identical fp32 ops to reference) -----
    const float thr = __fdiv_rn(__fmul_rn(*alpha, 8.0f), 15.0f);
    const float coef[4] = {0.9375f, 0.875f, 0.75f, 0.5f};

    #pragma unroll 1
    for (int r = 0; r < RPT; r++) {
        #pragma unroll 1
        for (int c = 0; c < CPT; c++) {
            int co = co0 + c;
            float mem[PX];
            #pragma unroll
            for (int p = 0; p < PX; p++)
                mem[p] = mymem[((r*CPT + c)*PX + p)*NTHREADS];
            float* obase = out + (b*T_*COUT_ + co)*HW_ + (oh0 + r)*W_ + ow0;
            #pragma unroll
            for (int dt = 0; dt < 4; dt++) {
                float cthr = __fmul_rn(coef[dt], thr);
                float4 o;
                float s0 = (mem[0] >= cthr) ? thr : 0.f; mem[0] = __fmul_rn(__fsub_rn(mem[0], s0), 2.f);
                float s1 = (mem[1] >= cthr) ? thr : 0.f; mem[1] = __fmul_rn(__fsub_rn(mem[1], s1), 2.f);
                float s2 = (mem[2] >= cthr) ? thr : 0.f; mem[2] = __fmul_rn(__fsub_rn(mem[2], s2), 2.f);
                float s3 = (mem[3] >= cthr) ? thr : 0.f; mem[3] = __fmul_rn(__fsub_rn(mem[3], s3), 2.f);
                o.x = s0; o.y = s1; o.z = s2; o.w = s3;
                *(float4*)(obase + dt*COUT_*HW_) = o;
            }
        }
    }
}

// ---------------------------------------------------------------------------
extern "C" void kernel_launch(void* const* d_in, const int* in_sizes, int n_in,
                              void* d_out, int out_size) {
    const float* x     = (const float*)d_in[0];
    const float* convw = (const float*)d_in[1];
    const float* convb = (const float*)d_in[2];
    const float* gamma = (const float*)d_in[3];
    const float* beta  = (const float*)d_in[4];
    const float* rmean = (const float*)d_in[5];
    const float* rvar  = (const float*)d_in[6];
    const float* alpha = (const float*)d_in[7];
    float* out = (float*)d_out;

    cudaFuncSetAttribute(conv_spike_kernel,
                         cudaFuncAttributeMaxDynamicSharedMemorySize,
                         SMEM_BYTES);

    wt_kernel<<<(COUT_*CIN_*9 + 255)/256, 256>>>(convw);

    dim3 grid(H_/RPT, COUT_/CT, B_);   // 28 x 2 x 16 = 896 CTAs
    conv_spike_kernel<<<grid, NTHREADS, SMEM_BYTES>>>(x, convb, gamma, beta,
                                                      rmean, rvar, alpha, out);
}

// round 13
// speedup vs baseline: 1.4574x; 1.0611x over previous
#include <cuda_runtime.h>
#include <math.h>

#define B_    16
#define T_    4
#define CIN_  128
#define COUT_ 128
#define H_    56
#define W_    56
#define HW_   (H_*W_)

#define CT    64     // couts per block
#define CPT   4      // couts per thread
#define PX    4      // pixels per thread
#define RPT   2      // output rows per thread (share weight loads)
#define NTHREADS 224 // cg = tid&15 (16 cout-groups), wg = tid>>4 (14 width-groups)
#define NCTAS (28*2*16)                // 896
#define MSLOTS (RPT*CPT*PX)            // 32 membrane slots per thread

// dynamic smem: s_in[2][128][60] — two staged input rows
// idx k holds input col (k-1): cols -1..56 at 0..57
#define SROW   60
#define SMEM_BYTES (2*CIN_*SROW*4)     // 61440 -> 3 CTAs/SM (184KB of 228KB)

typedef unsigned long long u64;

// transposed weights: wT[kh][kw][ci][co]
__device__ float g_wT[9*CIN_*COUT_];
// membrane scratch: [cta][slot][tid] — coalesced per slot, L2-resident (25.7MB)
__device__ float g_mem[NCTAS*MSLOTS*NTHREADS];

// ---------------------------------------------------------------------------
__global__ void wt_kernel(const float* __restrict__ w) {
    int i = blockIdx.x*256 + threadIdx.x;          // over co*ci*9
    if (i >= COUT_*CIN_*9) return;
    int co  = i / (CIN_*9);
    int rem = i - co*(CIN_*9);
    int ci  = rem / 9;
    int k   = rem - ci*9;
    g_wT[(k*CIN_ + ci)*COUT_ + co] = w[i];
}

// ---------------------------------------------------------------------------
// Packed fp32x2 helpers. Each lane of fma.rn.f32x2 rounds identically to
// scalar FFMA, so a packed chain == two independent scalar chains bitwise.
// ---------------------------------------------------------------------------
__device__ __forceinline__ void ffma2(u64 &d, u64 a, u64 b) {
    asm("fma.rn.f32x2 %0, %1, %2, %0;" : "+l"(d) : "l"(a), "l"(b));
}
__device__ __forceinline__ u64 pack2(float v) {   // {v, v} — 1 MOV in SASS
    u64 r; asm("mov.b64 %0, {%1, %1};" : "=l"(r) : "f"(v)); return r;
}
__device__ __forceinline__ void unpack2(u64 v, float &lo, float &hi) {
    asm("mov.b64 {%0, %1}, %2;" : "=f"(lo), "=f"(hi) : "l"(v));
}

// one (row) step: weight pair WP x 4 dup'd inputs -> 8 FFMA2 into row r's accs
#define ROW_STEP(R, WP, I0, I1, I2, I3)                                         \
    do {                                                                        \
        ffma2(acc2[R][0][0], (WP).x, (I0)); ffma2(acc2[R][1][0], (WP).y, (I0)); \
        ffma2(acc2[R][0][1], (WP).x, (I1)); ffma2(acc2[R][1][1], (WP).y, (I1)); \
        ffma2(acc2[R][0][2], (WP).x, (I2)); ffma2(acc2[R][1][2], (WP).y, (I2)); \
        ffma2(acc2[R][0][3], (WP).x, (I3)); ffma2(acc2[R][1][3], (WP).y, (I3)); \
    } while (0)

// ---------------------------------------------------------------------------
// Conv, reference-order chain k = (kh major, kw, ci minor); one fp32
// accumulator per output (packed in cout-pairs). kh outer -> stage the two
// input rows both thread-rows need. Thread: 4 couts x 4 px x 2 rows.
// Membrane lives in global scratch (L2) so smem allows 3 CTAs/SM.
// ---------------------------------------------------------------------------
__global__ __launch_bounds__(NTHREADS, 3)
void conv_spike_kernel(const float* __restrict__ x,
                       const float* __restrict__ cbias,
                       const float* __restrict__ gamma,
                       const float* __restrict__ beta,
                       const float* __restrict__ rmean,
                       const float* __restrict__ rvar,
                       const float* __restrict__ alpha,
                       float* __restrict__ out)
{
    extern __shared__ __align__(16) float s_in[];  // [2][128][60]

    const int oh0 = blockIdx.x * RPT;  // rows oh0, oh0+1
    const int ct  = blockIdx.y;        // 0..1
    const int b   = blockIdx.z;        // 0..15
    const int tid = threadIdx.x;       // 0..223
    const int cg  = tid & 15;          // cout group (fast across lanes)
    const int wg  = tid >> 4;          // width group 0..13
    const int ow0 = wg*PX;
    const int co0 = ct*CT + cg*CPT;
    const int ctaFlat = blockIdx.x + 28*(blockIdx.y + 2*blockIdx.z);
    float* mymem = g_mem + ctaFlat*MSLOTS*NTHREADS + tid;  // slot i at [i*NTHREADS]

    #pragma unroll 1
    for (int t = 0; t < T_; t++) {
        const float* xbt = x + (b*T_ + t)*CIN_*HW_;

        // fp32 accumulators: [row][cout-pair][pixel]
        u64 acc2[RPT][CPT/2][PX];
        #pragma unroll
        for (int r = 0; r < RPT; r++)
            #pragma unroll
            for (int q = 0; q < CPT/2; q++)
                #pragma unroll
                for (int p = 0; p < PX; p++) acc2[r][q][p] = 0ull;

        #pragma unroll 1
        for (int kh = 0; kh < 3; kh++) {
            __syncthreads();           // previous sweep done before overwrite
            // stage rows: slot s holds input row oh0-1+kh+s  (s = 0,1)
            #pragma unroll 1
            for (int idx = tid; idx < 2*CIN_*14; idx += NTHREADS) {
                int s   = idx / (CIN_*14);
                int rem = idx - s*(CIN_*14);
                int ci  = rem / 14;
                int g   = rem - ci*14;
                int ih  = oh0 - 1 + kh + s;
                float* d = s_in + (s*CIN_ + ci)*SROW + 1 + g*4;
                if ((unsigned)ih < (unsigned)H_) {
                    float4 v = *(const float4*)(xbt + ci*HW_ + ih*W_ + g*4);
                    d[0] = v.x; d[1] = v.y; d[2] = v.z; d[3] = v.w;
                } else {
                    d[0] = 0.f; d[1] = 0.f; d[2] = 0.f; d[3] = 0.f;
                }
            }
            // halo columns (idx 0 and 57) zero for both slots
            #pragma unroll 1
            for (int sc = tid; sc < 2*CIN_; sc += NTHREADS) {
                s_in[sc*SROW]      = 0.f;
                s_in[sc*SROW + 57] = 0.f;
            }
            __syncthreads();

            // chain: kw 0..2 in order, ci 0..127 inner (reference k-order);
            // one 16B weight load serves both rows (16 FFMA2).
            {   // kw = 0: idx ow0..ow0+3 (16B-aligned)
                const float* wt = g_wT + ((kh*3 + 0)*CIN_)*COUT_ + co0;
                const float* i0 = s_in + ow0;              // slot 0
                const float* i1 = s_in + CIN_*SROW + ow0;  // slot 1
                #pragma unroll 4
                for (int ci = 0; ci < CIN_; ci++) {
                    ulonglong2 wp = *(const ulonglong2*)(wt + ci*COUT_);
                    float4 a = *(const float4*)(i0 + ci*SROW);
                    float4 bv = *(const float4*)(i1 + ci*SROW);
                    ROW_STEP(0, wp, pack2(a.x), pack2(a.y), pack2(a.z), pack2(a.w));
                    ROW_STEP(1, wp, pack2(bv.x), pack2(bv.y), pack2(bv.z), pack2(bv.w));
                }
            }
            {   // kw = 1: idx ow0+1..ow0+4 -> LDS.128 (.y.z.w) + LDS.32
                const float* wt = g_wT + ((kh*3 + 1)*CIN_)*COUT_ + co0;
                const float* i0 = s_in + ow0;
                const float* i1 = s_in + CIN_*SROW + ow0;
                #pragma unroll 4
                for (int ci = 0; ci < CIN_; ci++) {
                    ulonglong2 wp = *(const ulonglong2*)(wt + ci*COUT_);
                    float4 a = *(const float4*)(i0 + ci*SROW);
                    float  a4 = i0[ci*SROW + 4];
                    float4 bv = *(const float4*)(i1 + ci*SROW);
                    float  b4 = i1[ci*SROW + 4];
                    ROW_STEP(0, wp, pack2(a.y), pack2(a.z), pack2(a.w), pack2(a4));
                    ROW_STEP(1, wp, pack2(bv.y), pack2(bv.z), pack2(bv.w), pack2(b4));
                }
            }
            {   // kw = 2: idx ow0+2..ow0+5 -> 2x LDS.64 per row
                const float* wt = g_wT + ((kh*3 + 2)*CIN_)*COUT_ + co0;
                const float* i0 = s_in + ow0 + 2;
                const float* i1 = s_in + CIN_*SROW + ow0 + 2;
                #pragma unroll 4
                for (int ci = 0; ci < CIN_; ci++) {
                    ulonglong2 wp = *(const ulonglong2*)(wt + ci*COUT_);
                    float2 a01 = *(const float2*)(i0 + ci*SROW);
                    float2 a23 = *(const float2*)(i0 + ci*SROW + 2);
                    float2 b01 = *(const float2*)(i1 + ci*SROW);
                    float2 b23 = *(const float2*)(i1 + ci*SROW + 2);
                    ROW_STEP(0, wp, pack2(a01.x), pack2(a01.y), pack2(a23.x), pack2(a23.y));
                    ROW_STEP(1, wp, pack2(b01.x), pack2(b01.y), pack2(b23.x), pack2(b23.y));
                }
            }
        }

        // --- per-timestep epilogue: replicate reference fp32 roundings ---
        const float tscale = (float)(1 << (3 - t));   // exact power of 2
        #pragma unroll 1
        for (int c = 0; c < CPT; c++) {
            int co = co0 + c;
            float cb = cbias[co];
            float mn = rmean[co];
            float iv = __fmul_rn(__fdiv_rn(1.0f, __fsqrt_rn(__fadd_rn(rvar[co], 1e-5f))),
                                 gamma[co]);
            float bt = beta[co];
            int q = c >> 1, half = c & 1;
            #pragma unroll
            for (int r = 0; r < RPT; r++) {
                #pragma unroll
                for (int p = 0; p < PX; p++) {
                    float al, ah;
                    unpack2(acc2[r][q][p], al, ah);
                    float y = half ? ah : al;                  // raw conv accumulator
                    y = __fadd_rn(y, cb);                      // + bias
                    y = __fmul_rn(y, 1.875f);                  // * (2^T-1)/2^(T-1)
                    y = __fmul_rn(__fsub_rn(y, mn), iv);       // BN sub, mul
                    y = __fadd_rn(y, bt);                      // + beta
                    y = __fdiv_rn(y, 15.0f);                   // / (2^T-1)
                    float prod = __fmul_rn(y, tscale);         // exact (power of 2)
                    int mi = ((r*CPT + c)*PX + p)*NTHREADS;    // coalesced slot
                    mymem[mi] = (t == 0) ? prod : __fadd_rn(mymem[mi], prod);
                }
            }
        }
    }

    // ----- spike scan (identical fp32 ops to reference) -----
    const float thr = __fdiv_rn(__fmul_rn(*alpha, 8.0f), 15.0f);
    const float coef[4] = {0.9375f, 0.875f, 0.75f, 0.5f};

    #pragma unroll 1
    for (int r = 0; r < RPT; r++) {
        #pragma unroll 1
        for (int c = 0; c < CPT; c++) {
            int co = co0 + c;
            float mem[PX];
            #pragma unroll
            for (int p = 0; p < PX; p++)
                mem[p] = mymem[((r*CPT + c)*PX + p)*NTHREADS];
            float* obase = out + (b*T_*COUT_ + co)*HW_ + (oh0 + r)*W_ + ow0;
            #pragma unroll
            for (int dt = 0; dt < 4; dt++) {
                float cthr = __fmul_rn(coef[dt], thr);
                float4 o;
                float s0 = (mem[0] >= cthr) ? thr : 0.f; mem[0] = __fmul_rn(__fsub_rn(mem[0], s0), 2.f);
                float s1 = (mem[1] >= cthr) ? thr : 0.f; mem[1] = __fmul_rn(__fsub_rn(mem[1], s1), 2.f);
                float s2 = (mem[2] >= cthr) ? thr : 0.f; mem[2] = __fmul_rn(__fsub_rn(mem[2], s2), 2.f);
                float s3 = (mem[3] >= cthr) ? thr : 0.f; mem[3] = __fmul_rn(__fsub_rn(mem[3], s3), 2.f);
                o.x = s0; o.y = s1; o.z = s2; o.w = s3;
                *(float4*)(obase + dt*COUT_*HW_) = o;
            }
        }
    }
}

// ---------------------------------------------------------------------------
extern "C" void kernel_launch(void* const* d_in, const int* in_sizes, int n_in,
                              void* d_out, int out_size) {
    const float* x     = (const float*)d_in[0];
    const float* convw = (const float*)d_in[1];
    const float* convb = (const float*)d_in[2];
    const float* gamma = (const float*)d_in[3];
    const float* beta  = (const float*)d_in[4];
    const float* rmean = (const float*)d_in[5];
    const float* rvar  = (const float*)d_in[6];
    const float* alpha = (const float*)d_in[7];
    float* out = (float*)d_out;

    cudaFuncSetAttribute(conv_spike_kernel,
                         cudaFuncAttributeMaxDynamicSharedMemorySize,
                         SMEM_BYTES);

    wt_kernel<<<(COUT_*CIN_*9 + 255)/256, 256>>>(convw);

    dim3 grid(H_/RPT, COUT_/CT, B_);   // 28 x 2 x 16 = 896 CTAs
    conv_spike_kernel<<<grid, NTHREADS, SMEM_BYTES>>>(x, convb, gamma, beta,
                                                      rmean, rvar, alpha, out);
}